// round 8
// baseline (speedup 1.0000x reference)
#include <cuda_runtime.h>
#include <cstdint>

// ---------------------------------------------------------------------------
// Problem constants (fixed by the dataset)
// ---------------------------------------------------------------------------
#define T_STEPS   1000
#define T_PAD     1008          // multiple of 16 for mma tiles
#define N_IN      700
#define K_PAD     704           // multiple of 32 for mma k
#define N_HID     4096
#define N_OUT     20
#define SP_STRIDE 4096          // max spikes per step (full safety)

// ---------------------------------------------------------------------------
// Static device scratch (no runtime allocation)
// ---------------------------------------------------------------------------
__device__ int            g_esize;                       // 8|4|-4|-8
__device__ int8_t         g_spk [T_PAD * K_PAD];         // spikes int8, padded
__device__ int8_t         g_w1s [N_HID * K_PAD];         // w1 int8, padded
__device__ int8_t         g_v1T [(size_t)N_HID * N_HID]; // v1T[k][h] = v1[h][k]
__device__ int8_t         g_w2T [N_HID * N_OUT];         // w2T[k][o] = w2[o][k]
__device__ int            g_in  [T_PAD * N_HID];         // feed-forward currents
__device__ unsigned short g_list[(size_t)T_STEPS * SP_STRIDE]; // spike ids/step
__device__ int            g_cnt [T_STEPS];               // spike count/step
__device__ int            g_ro  [T_STEPS * N_OUT];       // readout currents

// ---------------------------------------------------------------------------
// Dtype-agnostic element load (values all fit int; conversions exact)
// ---------------------------------------------------------------------------
__device__ __forceinline__ int load_elem(const void* p, int es, size_t i) {
    if (es == 8)  return (int)((const long long*)p)[i];
    if (es == 4)  return ((const int*)p)[i];
    if (es == -4) return (int)((const float*)p)[i];
    return (int)((const double*)p)[i];
}

// ---------------------------------------------------------------------------
// Dtype sniffing on w2's raw words (values uniform in [-8,8)).
// ---------------------------------------------------------------------------
__global__ void k_detect(const void* __restrict__ w2) {
    const unsigned* u = (const unsigned*)w2;
    int is_float = 0, odd_ok = 1, even_nz = 0;
    for (int i = 0; i < 512; ++i) {
        unsigned w = u[i];
        unsigned e = (w >> 23) & 0xFFu;
        if (w != 0u && e >= 0x70u && e <= 0x90u) is_float = 1;
        if (i & 1) { if (w != 0u && w != 0xFFFFFFFFu) odd_ok = 0; }
        else       { if (w != 0u) even_nz = 1; }
    }
    g_esize = is_float ? (even_nz ? -4 : -8) : (odd_ok ? 8 : 4);
}

// ---------------------------------------------------------------------------
// Pack kernels
// ---------------------------------------------------------------------------
__global__ void k_pack_spk(const void* __restrict__ spk) {
    int es = g_esize;
    int idx = blockIdx.x * blockDim.x + threadIdx.x;
    if (idx >= T_PAD * K_PAD) return;
    int t = idx / K_PAD, i = idx % K_PAD;
    int8_t v = 0;
    if (t < T_STEPS && i < N_IN) v = (int8_t)load_elem(spk, es, (size_t)t * N_IN + i);
    g_spk[idx] = v;
}

__global__ void k_pack_w1(const void* __restrict__ w1) {
    int es = g_esize;
    int idx = blockIdx.x * blockDim.x + threadIdx.x;
    if (idx >= N_HID * K_PAD) return;
    int h = idx / K_PAD, i = idx % K_PAD;
    int8_t v = 0;
    if (i < N_IN) v = (int8_t)load_elem(w1, es, (size_t)h * N_IN + i);
    g_w1s[idx] = v;
}

// w2[o][k] -> w2T[k][o] int8 (so per-spike readout reads 20 contiguous bytes)
__global__ void k_pack_w2(const void* __restrict__ w2) {
    int es = g_esize;
    int idx = blockIdx.x * blockDim.x + threadIdx.x;
    if (idx >= N_OUT * N_HID) return;
    int o = idx / N_HID, k = idx % N_HID;
    g_w2T[k * N_OUT + o] = (int8_t)load_elem(w2, es, (size_t)idx);
}

// Tiled transpose v1[h][k] -> v1T[k][h] (int8)
__global__ void k_v1_transpose(const void* __restrict__ v1) {
    __shared__ int8_t tile[32][33];
    int es = g_esize;
    int bk = blockIdx.x * 32;
    int bh = blockIdx.y * 32;
    int x = threadIdx.x, y = threadIdx.y;
    tile[y][x] = (int8_t)load_elem(v1, es, (size_t)(bh + y) * N_HID + (bk + x));
    __syncthreads();
    g_v1T[(size_t)(bk + y) * N_HID + (bh + x)] = tile[x][y];
}

// ---------------------------------------------------------------------------
// in_all GEMM: g_in[t][h] = sum_i g_spk[t][i] * g_w1s[h][i]
// Each warp computes a 16(T) x 64(H) tile: A fragment reused across 8 N-tiles.
// ---------------------------------------------------------------------------
__global__ __launch_bounds__(256) void k_gemm_in() {
    int warp = (blockIdx.x * blockDim.x + threadIdx.x) >> 5;
    int lane = threadIdx.x & 31;
    int tt = warp / (N_HID / 64);
    int hh = warp % (N_HID / 64);
    int T0 = tt * 16;
    int H0 = hh * 64;

    int grp = lane >> 2;
    int tig = lane & 3;

    int acc[8][4];
    #pragma unroll
    for (int nt = 0; nt < 8; ++nt)
        acc[nt][0] = acc[nt][1] = acc[nt][2] = acc[nt][3] = 0;

    const int8_t* arow0 = g_spk + (size_t)(T0 + grp)     * K_PAD;
    const int8_t* arow1 = g_spk + (size_t)(T0 + grp + 8) * K_PAD;

    for (int k0 = 0; k0 < K_PAD; k0 += 32) {
        int a0 = *(const int*)(arow0 + k0 + tig * 4);
        int a1 = *(const int*)(arow1 + k0 + tig * 4);
        int a2 = *(const int*)(arow0 + k0 + 16 + tig * 4);
        int a3 = *(const int*)(arow1 + k0 + 16 + tig * 4);
        #pragma unroll
        for (int nt = 0; nt < 8; ++nt) {
            const int8_t* brow = g_w1s + (size_t)(H0 + nt * 8 + grp) * K_PAD;
            int b0 = *(const int*)(brow + k0 + tig * 4);
            int b1 = *(const int*)(brow + k0 + 16 + tig * 4);
            asm volatile(
                "mma.sync.aligned.m16n8k32.row.col.s32.s8.s8.s32 "
                "{%0,%1,%2,%3}, {%4,%5,%6,%7}, {%8,%9}, {%0,%1,%2,%3};"
                : "+r"(acc[nt][0]), "+r"(acc[nt][1]), "+r"(acc[nt][2]), "+r"(acc[nt][3])
                : "r"(a0), "r"(a1), "r"(a2), "r"(a3), "r"(b0), "r"(b1));
        }
    }

    #pragma unroll
    for (int nt = 0; nt < 8; ++nt) {
        int* out0 = g_in + (size_t)(T0 + grp)     * N_HID + H0 + nt * 8 + tig * 2;
        int* out1 = g_in + (size_t)(T0 + grp + 8) * N_HID + H0 + nt * 8 + tig * 2;
        out0[0] = acc[nt][0];  out0[1] = acc[nt][1];
        out1[0] = acc[nt][2];  out1[1] = acc[nt][3];
    }
}

// ---------------------------------------------------------------------------
// Persistent single-CTA recurrent kernel — hidden layer ONLY.
// Readout is deferred to post-kernels (it is a linear filter of the spike
// train and never feeds back). Loop: gather fb -> LIF -> record spikes ->
// single barrier.
//
// Sync audit (1 __syncthreads per step):
//   lists double-buffered: gather(t) reads L[(t-1)&1]; LIF(t+1) overwrites it
//     after BAR(t). LIF(t) writes L[t&1]; gather(t+1) reads it after BAR(t).
//   counters triple-buffered (read/write/zero rotation): zeroed buffer was
//     last read before the previous barrier and next written after this one.
//   g_cnt[t] STG by tid0 post-barrier (all atomics complete); consumed only
//   by later kernels (kernel-boundary sync).
// ---------------------------------------------------------------------------
__global__ __launch_bounds__(1024, 1) void k_persist()
{
    __shared__ unsigned short list0[N_HID];
    __shared__ unsigned short list1[N_HID];
    __shared__ int cnt[3];

    const int tid = threadIdx.x;
    if (tid == 0) { cnt[0] = 0; cnt[1] = 0; cnt[2] = 0; }
    __syncthreads();

    int mem0 = 0, mem1 = 0, mem2 = 0, mem3 = 0;
    int syn0 = 0, syn1 = 0, syn2 = 0, syn3 = 0;
    unsigned prev = 0;

    const int hbase = tid * 4;

    int ir = 2, iw = 0, iz = 1;     // counter rotation: read, write, zero

    for (int t = 0; t < T_STEPS; ++t) {
        unsigned short* wr = (t & 1) ? list1 : list0;   // written this step
        unsigned short* rd = (t & 1) ? list0 : list1;   // written at t-1

        // feed-forward currents for this step (issues first, overlaps gather)
        const int4 inv = *(const int4*)(g_in + (size_t)t * N_HID + hbase);

        // sparse recurrent feedback from spikes(t-1); 16-deep predicated batch
        int n = cnt[ir];
        int fb0 = 0, fb1 = 0, fb2 = 0, fb3 = 0;
        for (int base = 0; base < n; base += 16) {
            int w[16];
            #pragma unroll
            for (int j = 0; j < 16; ++j) {
                w[j] = 0;
                if (base + j < n) {
                    int k = rd[base + j];
                    w[j] = *(const int*)(g_v1T + (size_t)k * N_HID + hbase);
                }
            }
            #pragma unroll
            for (int j = 0; j < 16; ++j) {
                fb0 += (w[j] << 24) >> 24;
                fb1 += (w[j] << 16) >> 24;
                fb2 += (w[j] <<  8) >> 24;
                fb3 +=  w[j] >> 24;
            }
        }

        // hidden LIF: reset -> threshold -> decay/integrate; record spikes
        unsigned short* gl = g_list + (size_t)t * SP_STRIDE;
        unsigned newprev = 0;
        {
            int m, o;
            m = (prev & 1u) ? 0 : mem0;  o = (m > 1);
            mem0 = m - (m >> 3) + syn0;
            syn0 = syn0 - (syn0 >> 4) + inv.x + fb0;
            if (o) { int pos = atomicAdd(&cnt[iw], 1);
                     wr[pos] = (unsigned short)(hbase + 0);
                     gl[pos] = (unsigned short)(hbase + 0); newprev |= 1u; }

            m = (prev & 2u) ? 0 : mem1;  o = (m > 1);
            mem1 = m - (m >> 3) + syn1;
            syn1 = syn1 - (syn1 >> 4) + inv.y + fb1;
            if (o) { int pos = atomicAdd(&cnt[iw], 1);
                     wr[pos] = (unsigned short)(hbase + 1);
                     gl[pos] = (unsigned short)(hbase + 1); newprev |= 2u; }

            m = (prev & 4u) ? 0 : mem2;  o = (m > 1);
            mem2 = m - (m >> 3) + syn2;
            syn2 = syn2 - (syn2 >> 4) + inv.z + fb2;
            if (o) { int pos = atomicAdd(&cnt[iw], 1);
                     wr[pos] = (unsigned short)(hbase + 2);
                     gl[pos] = (unsigned short)(hbase + 2); newprev |= 4u; }

            m = (prev & 8u) ? 0 : mem3;  o = (m > 1);
            mem3 = m - (m >> 3) + syn3;
            syn3 = syn3 - (syn3 >> 4) + inv.w + fb3;
            if (o) { int pos = atomicAdd(&cnt[iw], 1);
                     wr[pos] = (unsigned short)(hbase + 3);
                     gl[pos] = (unsigned short)(hbase + 3); newprev |= 8u; }
        }
        prev = newprev;

        if (tid == 0) cnt[iz] = 0;             // recycle for step t+1

        __syncthreads();                        // single barrier per step

        if (tid == 0) g_cnt[t] = cnt[iw];       // publish count (post-barrier)

        // rotate counter roles
        int t0 = ir; ir = iw; iw = iz; iz = t0;
    }
}

// ---------------------------------------------------------------------------
// Readout currents: ro[t][o] = sum_{k in spikes(t)} w2T[k][o]
// 1000 independent blocks; w2T is L2-resident (80 KB).
// ---------------------------------------------------------------------------
__global__ __launch_bounds__(32) void k_rocur() {
    int t = blockIdx.x;
    int o = threadIdx.x;
    int n = g_cnt[t];
    const unsigned short* gl = g_list + (size_t)t * SP_STRIDE;
    int ro = 0;
    if (o < N_OUT) {
        for (int i = 0; i < n; ++i) {
            int k = gl[i];
            ro += g_w2T[k * N_OUT + o];
        }
        g_ro[t * N_OUT + o] = ro;
    }
}

// ---------------------------------------------------------------------------
// Readout LIF scan: 20 threads, each scans its output over 1000 steps.
// Loads are independent of state -> prefetched by unrolling.
// ---------------------------------------------------------------------------
__global__ __launch_bounds__(32) void k_roscan(float* __restrict__ out) {
    int o = threadIdx.x;
    if (o >= N_OUT) return;
    int rmem = 0, rsyn = 0;
    for (int t = 0; t < T_STEPS; t += 4) {
        int r0 = g_ro[(t + 0) * N_OUT + o];
        int r1 = g_ro[(t + 1) * N_OUT + o];
        int r2 = g_ro[(t + 2) * N_OUT + o];
        int r3 = g_ro[(t + 3) * N_OUT + o];
        rmem = rmem - (rmem >> 3) + rsyn;  rsyn = rsyn - (rsyn >> 4) + r0;
        out[(size_t)o * T_STEPS + t + 0] = (float)rmem;
        rmem = rmem - (rmem >> 3) + rsyn;  rsyn = rsyn - (rsyn >> 4) + r1;
        out[(size_t)o * T_STEPS + t + 1] = (float)rmem;
        rmem = rmem - (rmem >> 3) + rsyn;  rsyn = rsyn - (rsyn >> 4) + r2;
        out[(size_t)o * T_STEPS + t + 2] = (float)rmem;
        rmem = rmem - (rmem >> 3) + rsyn;  rsyn = rsyn - (rsyn >> 4) + r3;
        out[(size_t)o * T_STEPS + t + 3] = (float)rmem;
    }
}

// ---------------------------------------------------------------------------
// Launch
// ---------------------------------------------------------------------------
extern "C" void kernel_launch(void* const* d_in, const int* in_sizes, int n_in,
                              void* d_out, int out_size) {
    // Robust input identification: all element counts are distinct.
    const void* spk = d_in[0];
    const void* w1  = d_in[1];
    const void* v1  = d_in[2];
    const void* w2  = d_in[3];
    for (int i = 0; i < n_in && i < 4; ++i) {
        int s = in_sizes[i];
        if      (s == T_STEPS * N_IN)  spk = d_in[i];
        else if (s == N_HID * N_IN)    w1  = d_in[i];
        else if (s == N_HID * N_HID)   v1  = d_in[i];
        else if (s == N_OUT * N_HID)   w2  = d_in[i];
    }

    k_detect<<<1, 1>>>(w2);

    k_pack_spk<<<(T_PAD * K_PAD + 255) / 256, 256>>>(spk);
    k_pack_w1 <<<(N_HID * K_PAD + 255) / 256, 256>>>(w1);
    k_pack_w2 <<<(N_OUT * N_HID + 255) / 256, 256>>>(w2);
    k_v1_transpose<<<dim3(N_HID / 32, N_HID / 32), dim3(32, 32)>>>(v1);

    k_gemm_in<<<(T_PAD / 16) * (N_HID / 64) / 8, 256>>>();

    k_persist<<<1, 1024>>>();

    k_rocur<<<T_STEPS, 32>>>();
    k_roscan<<<1, 32>>>((float*)d_out);
}

// round 9
// speedup vs baseline: 1.5586x; 1.5586x over previous
#include <cuda_runtime.h>
#include <cstdint>

// ---------------------------------------------------------------------------
// Problem constants (fixed by the dataset)
// ---------------------------------------------------------------------------
#define T_STEPS   1000
#define T_PAD     1008          // multiple of 16 for mma tiles
#define N_IN      700
#define K_PAD     704           // multiple of 32 for mma k
#define N_HID     4096
#define N_OUT     20
#define SP_STRIDE 4096          // max spikes per step (full safety)

// ---------------------------------------------------------------------------
// Static device scratch (no runtime allocation)
// ---------------------------------------------------------------------------
__device__ int            g_esize;                       // 8|4|-4|-8
__device__ int8_t         g_spk [T_PAD * K_PAD];         // spikes int8, padded
__device__ int8_t         g_w1s [N_HID * K_PAD];         // w1 int8, padded
__device__ int8_t         g_v1T [(size_t)N_HID * N_HID]; // v1T[k][h] = v1[h][k]
__device__ int8_t         g_w2T [N_HID * N_OUT];         // w2T[k][o] = w2[o][k]
__device__ int            g_in  [T_PAD * N_HID];         // feed-forward currents
__device__ unsigned short g_list[(size_t)T_STEPS * SP_STRIDE]; // spike ids/step
__device__ int            g_cnt [T_STEPS];               // spike count/step
__device__ int            g_ro  [T_STEPS * N_OUT];       // readout currents

// ---------------------------------------------------------------------------
// Dtype-agnostic element load (values all fit int; conversions exact)
// ---------------------------------------------------------------------------
__device__ __forceinline__ int load_elem(const void* p, int es, size_t i) {
    if (es == 8)  return (int)((const long long*)p)[i];
    if (es == 4)  return ((const int*)p)[i];
    if (es == -4) return (int)((const float*)p)[i];
    return (int)((const double*)p)[i];
}

// ---------------------------------------------------------------------------
// Dtype sniffing on w2's raw words (values uniform in [-8,8)).
// ---------------------------------------------------------------------------
__global__ void k_detect(const void* __restrict__ w2) {
    const unsigned* u = (const unsigned*)w2;
    int is_float = 0, odd_ok = 1, even_nz = 0;
    for (int i = 0; i < 512; ++i) {
        unsigned w = u[i];
        unsigned e = (w >> 23) & 0xFFu;
        if (w != 0u && e >= 0x70u && e <= 0x90u) is_float = 1;
        if (i & 1) { if (w != 0u && w != 0xFFFFFFFFu) odd_ok = 0; }
        else       { if (w != 0u) even_nz = 1; }
    }
    g_esize = is_float ? (even_nz ? -4 : -8) : (odd_ok ? 8 : 4);
}

// ---------------------------------------------------------------------------
// Pack kernels
// ---------------------------------------------------------------------------
__global__ void k_pack_spk(const void* __restrict__ spk) {
    int es = g_esize;
    int idx = blockIdx.x * blockDim.x + threadIdx.x;
    if (idx >= T_PAD * K_PAD) return;
    int t = idx / K_PAD, i = idx % K_PAD;
    int8_t v = 0;
    if (t < T_STEPS && i < N_IN) v = (int8_t)load_elem(spk, es, (size_t)t * N_IN + i);
    g_spk[idx] = v;
}

__global__ void k_pack_w1(const void* __restrict__ w1) {
    int es = g_esize;
    int idx = blockIdx.x * blockDim.x + threadIdx.x;
    if (idx >= N_HID * K_PAD) return;
    int h = idx / K_PAD, i = idx % K_PAD;
    int8_t v = 0;
    if (i < N_IN) v = (int8_t)load_elem(w1, es, (size_t)h * N_IN + i);
    g_w1s[idx] = v;
}

// w2[o][k] -> w2T[k][o] int8 (per-spike readout reads 20 contiguous bytes)
__global__ void k_pack_w2(const void* __restrict__ w2) {
    int es = g_esize;
    int idx = blockIdx.x * blockDim.x + threadIdx.x;
    if (idx >= N_OUT * N_HID) return;
    int o = idx / N_HID, k = idx % N_HID;
    g_w2T[k * N_OUT + o] = (int8_t)load_elem(w2, es, (size_t)idx);
}

// Tiled transpose v1[h][k] -> v1T[k][h] (int8)
__global__ void k_v1_transpose(const void* __restrict__ v1) {
    __shared__ int8_t tile[32][33];
    int es = g_esize;
    int bk = blockIdx.x * 32;
    int bh = blockIdx.y * 32;
    int x = threadIdx.x, y = threadIdx.y;
    tile[y][x] = (int8_t)load_elem(v1, es, (size_t)(bh + y) * N_HID + (bk + x));
    __syncthreads();
    g_v1T[(size_t)(bk + y) * N_HID + (bh + x)] = tile[x][y];
}

// ---------------------------------------------------------------------------
// in_all GEMM: g_in[t][h] = sum_i g_spk[t][i] * g_w1s[h][i]
// Each warp computes a 16(T) x 64(H) tile: A fragment reused across 8 N-tiles.
// ---------------------------------------------------------------------------
__global__ __launch_bounds__(256) void k_gemm_in() {
    int warp = (blockIdx.x * blockDim.x + threadIdx.x) >> 5;
    int lane = threadIdx.x & 31;
    int tt = warp / (N_HID / 64);
    int hh = warp % (N_HID / 64);
    int T0 = tt * 16;
    int H0 = hh * 64;

    int grp = lane >> 2;
    int tig = lane & 3;

    int acc[8][4];
    #pragma unroll
    for (int nt = 0; nt < 8; ++nt)
        acc[nt][0] = acc[nt][1] = acc[nt][2] = acc[nt][3] = 0;

    const int8_t* arow0 = g_spk + (size_t)(T0 + grp)     * K_PAD;
    const int8_t* arow1 = g_spk + (size_t)(T0 + grp + 8) * K_PAD;

    for (int k0 = 0; k0 < K_PAD; k0 += 32) {
        int a0 = *(const int*)(arow0 + k0 + tig * 4);
        int a1 = *(const int*)(arow1 + k0 + tig * 4);
        int a2 = *(const int*)(arow0 + k0 + 16 + tig * 4);
        int a3 = *(const int*)(arow1 + k0 + 16 + tig * 4);
        #pragma unroll
        for (int nt = 0; nt < 8; ++nt) {
            const int8_t* brow = g_w1s + (size_t)(H0 + nt * 8 + grp) * K_PAD;
            int b0 = *(const int*)(brow + k0 + tig * 4);
            int b1 = *(const int*)(brow + k0 + 16 + tig * 4);
            asm volatile(
                "mma.sync.aligned.m16n8k32.row.col.s32.s8.s8.s32 "
                "{%0,%1,%2,%3}, {%4,%5,%6,%7}, {%8,%9}, {%0,%1,%2,%3};"
                : "+r"(acc[nt][0]), "+r"(acc[nt][1]), "+r"(acc[nt][2]), "+r"(acc[nt][3])
                : "r"(a0), "r"(a1), "r"(a2), "r"(a3), "r"(b0), "r"(b1));
        }
    }

    #pragma unroll
    for (int nt = 0; nt < 8; ++nt) {
        int* out0 = g_in + (size_t)(T0 + grp)     * N_HID + H0 + nt * 8 + tig * 2;
        int* out1 = g_in + (size_t)(T0 + grp + 8) * N_HID + H0 + nt * 8 + tig * 2;
        out0[0] = acc[nt][0];  out0[1] = acc[nt][1];
        out1[0] = acc[nt][2];  out1[1] = acc[nt][3];
    }
}

// ---------------------------------------------------------------------------
// Persistent single-CTA recurrent kernel — hidden layer only, readout
// deferred (linear filter of the spike train; no feedback).
//
// Per step: vectorized index read -> 8-deep batched v1T row gather with dp4a
// byte-lane accumulation -> LIF -> record spikes -> single barrier.
//
// Register budget (1024 thr => 64 regs cap): state 8 + fb 4 + w 8 + idx/ptr
// bookkeeping ~15 => ~40 live, no spills (R8's w[16] spilled; that was the
// regression).
//
// Sync audit (1 __syncthreads per step): lists double-buffered (RAW and WAR
// across steps separated by the barrier); counters triple-buffered
// read/write/zero; g_cnt STG post-barrier, consumed after kernel boundary.
// ---------------------------------------------------------------------------
__global__ __launch_bounds__(1024, 1) void k_persist()
{
    __shared__ __align__(16) unsigned short list0[N_HID + 8];  // +8: vector pad
    __shared__ __align__(16) unsigned short list1[N_HID + 8];
    __shared__ int cnt[3];

    const int tid = threadIdx.x;
    if (tid == 0) { cnt[0] = 0; cnt[1] = 0; cnt[2] = 0; }
    __syncthreads();

    int mem0 = 0, mem1 = 0, mem2 = 0, mem3 = 0;
    int syn0 = 0, syn1 = 0, syn2 = 0, syn3 = 0;
    unsigned prev = 0;

    const int hbase = tid * 4;
    const int8_t* v1col = g_v1T + hbase;

    int ir = 2, iw = 0, iz = 1;     // counter rotation: read, write, zero

    for (int t = 0; t < T_STEPS; ++t) {
        unsigned short* wr = (t & 1) ? list1 : list0;   // written this step
        unsigned short* rd = (t & 1) ? list0 : list1;   // written at t-1

        // feed-forward currents (independent load, overlaps gather)
        const int4 inv = *(const int4*)(g_in + (size_t)t * N_HID + hbase);

        // sparse recurrent feedback from spikes(t-1)
        int n = cnt[ir];
        int fb0 = 0, fb1 = 0, fb2 = 0, fb3 = 0;
        for (int base = 0; base < n; base += 8) {
            // 8 indices in one 16B shared load (broadcast, conflict-free)
            uint4 iv = *(const uint4*)(rd + base);
            int w[8];
            w[0] =                 *(const int*)(v1col + (size_t)(iv.x & 0xFFFF) * N_HID);
            w[1] = (base + 1 < n) ? *(const int*)(v1col + (size_t)(iv.x >> 16)   * N_HID) : 0;
            w[2] = (base + 2 < n) ? *(const int*)(v1col + (size_t)(iv.y & 0xFFFF)* N_HID) : 0;
            w[3] = (base + 3 < n) ? *(const int*)(v1col + (size_t)(iv.y >> 16)   * N_HID) : 0;
            w[4] = (base + 4 < n) ? *(const int*)(v1col + (size_t)(iv.z & 0xFFFF)* N_HID) : 0;
            w[5] = (base + 5 < n) ? *(const int*)(v1col + (size_t)(iv.z >> 16)   * N_HID) : 0;
            w[6] = (base + 6 < n) ? *(const int*)(v1col + (size_t)(iv.w & 0xFFFF)* N_HID) : 0;
            w[7] = (base + 7 < n) ? *(const int*)(v1col + (size_t)(iv.w >> 16)   * N_HID) : 0;
            #pragma unroll
            for (int j = 0; j < 8; ++j) {
                // dp4a with single-byte-lane selector: sign-extended byte sum
                fb0 = __dp4a(w[j], 0x00000001, fb0);
                fb1 = __dp4a(w[j], 0x00000100, fb1);
                fb2 = __dp4a(w[j], 0x00010000, fb2);
                fb3 = __dp4a(w[j], 0x01000000, fb3);
            }
        }

        // hidden LIF: reset -> threshold -> decay/integrate; record spikes
        unsigned short* gl = g_list + (size_t)t * SP_STRIDE;
        unsigned newprev = 0;
        {
            int m, o;
            m = (prev & 1u) ? 0 : mem0;  o = (m > 1);
            mem0 = m - (m >> 3) + syn0;
            syn0 = syn0 - (syn0 >> 4) + inv.x + fb0;
            if (o) { int pos = atomicAdd(&cnt[iw], 1);
                     wr[pos] = (unsigned short)(hbase + 0);
                     gl[pos] = (unsigned short)(hbase + 0); newprev |= 1u; }

            m = (prev & 2u) ? 0 : mem1;  o = (m > 1);
            mem1 = m - (m >> 3) + syn1;
            syn1 = syn1 - (syn1 >> 4) + inv.y + fb1;
            if (o) { int pos = atomicAdd(&cnt[iw], 1);
                     wr[pos] = (unsigned short)(hbase + 1);
                     gl[pos] = (unsigned short)(hbase + 1); newprev |= 2u; }

            m = (prev & 4u) ? 0 : mem2;  o = (m > 1);
            mem2 = m - (m >> 3) + syn2;
            syn2 = syn2 - (syn2 >> 4) + inv.z + fb2;
            if (o) { int pos = atomicAdd(&cnt[iw], 1);
                     wr[pos] = (unsigned short)(hbase + 2);
                     gl[pos] = (unsigned short)(hbase + 2); newprev |= 4u; }

            m = (prev & 8u) ? 0 : mem3;  o = (m > 1);
            mem3 = m - (m >> 3) + syn3;
            syn3 = syn3 - (syn3 >> 4) + inv.w + fb3;
            if (o) { int pos = atomicAdd(&cnt[iw], 1);
                     wr[pos] = (unsigned short)(hbase + 3);
                     gl[pos] = (unsigned short)(hbase + 3); newprev |= 8u; }
        }
        prev = newprev;

        if (tid == 0) cnt[iz] = 0;             // recycle for step t+1

        __syncthreads();                        // single barrier per step

        if (tid == 0) g_cnt[t] = cnt[iw];       // publish count (post-barrier)

        // rotate counter roles
        int t0 = ir; ir = iw; iw = iz; iz = t0;
    }
}

// ---------------------------------------------------------------------------
// Readout currents: ro[t][o] = sum_{k in spikes(t)} w2T[k][o]
// 1000 independent blocks; w2T is L2-resident (80 KB).
// ---------------------------------------------------------------------------
__global__ __launch_bounds__(32) void k_rocur() {
    int t = blockIdx.x;
    int o = threadIdx.x;
    int n = g_cnt[t];
    const unsigned short* gl = g_list + (size_t)t * SP_STRIDE;
    int ro = 0;
    if (o < N_OUT) {
        for (int i = 0; i < n; ++i) {
            int k = gl[i];
            ro += g_w2T[k * N_OUT + o];
        }
        g_ro[t * N_OUT + o] = ro;
    }
}

// ---------------------------------------------------------------------------
// Readout LIF scan: 20 threads, each scans its output over 1000 steps.
// ---------------------------------------------------------------------------
__global__ __launch_bounds__(32) void k_roscan(float* __restrict__ out) {
    int o = threadIdx.x;
    if (o >= N_OUT) return;
    int rmem = 0, rsyn = 0;
    for (int t = 0; t < T_STEPS; t += 4) {
        int r0 = g_ro[(t + 0) * N_OUT + o];
        int r1 = g_ro[(t + 1) * N_OUT + o];
        int r2 = g_ro[(t + 2) * N_OUT + o];
        int r3 = g_ro[(t + 3) * N_OUT + o];
        rmem = rmem - (rmem >> 3) + rsyn;  rsyn = rsyn - (rsyn >> 4) + r0;
        out[(size_t)o * T_STEPS + t + 0] = (float)rmem;
        rmem = rmem - (rmem >> 3) + rsyn;  rsyn = rsyn - (rsyn >> 4) + r1;
        out[(size_t)o * T_STEPS + t + 1] = (float)rmem;
        rmem = rmem - (rmem >> 3) + rsyn;  rsyn = rsyn - (rsyn >> 4) + r2;
        out[(size_t)o * T_STEPS + t + 2] = (float)rmem;
        rmem = rmem - (rmem >> 3) + rsyn;  rsyn = rsyn - (rsyn >> 4) + r3;
        out[(size_t)o * T_STEPS + t + 3] = (float)rmem;
    }
}

// ---------------------------------------------------------------------------
// Launch
// ---------------------------------------------------------------------------
extern "C" void kernel_launch(void* const* d_in, const int* in_sizes, int n_in,
                              void* d_out, int out_size) {
    // Robust input identification: all element counts are distinct.
    const void* spk = d_in[0];
    const void* w1  = d_in[1];
    const void* v1  = d_in[2];
    const void* w2  = d_in[3];
    for (int i = 0; i < n_in && i < 4; ++i) {
        int s = in_sizes[i];
        if      (s == T_STEPS * N_IN)  spk = d_in[i];
        else if (s == N_HID * N_IN)    w1  = d_in[i];
        else if (s == N_HID * N_HID)   v1  = d_in[i];
        else if (s == N_OUT * N_HID)   w2  = d_in[i];
    }

    k_detect<<<1, 1>>>(w2);

    k_pack_spk<<<(T_PAD * K_PAD + 255) / 256, 256>>>(spk);
    k_pack_w1 <<<(N_HID * K_PAD + 255) / 256, 256>>>(w1);
    k_pack_w2 <<<(N_OUT * N_HID + 255) / 256, 256>>>(w2);
    k_v1_transpose<<<dim3(N_HID / 32, N_HID / 32), dim3(32, 32)>>>(v1);

    k_gemm_in<<<(T_PAD / 16) * (N_HID / 64) / 8, 256>>>();

    k_persist<<<1, 1024>>>();

    k_rocur<<<T_STEPS, 32>>>();
    k_roscan<<<1, 32>>>((float*)d_out);
}

// round 12
// speedup vs baseline: 1.5772x; 1.0119x over previous
#include <cuda_runtime.h>
#include <cstdint>

// ---------------------------------------------------------------------------
// Problem constants (fixed by the dataset)
// ---------------------------------------------------------------------------
#define T_STEPS   1000
#define T_PAD     1008          // multiple of 16 for mma tiles
#define N_IN      700
#define K_PAD     704           // multiple of 32 for mma k
#define N_HID     4096
#define N_OUT     20
#define SP_STRIDE 4096          // max spikes per step (full safety)

// ---------------------------------------------------------------------------
// Static device scratch (no runtime allocation)
// ---------------------------------------------------------------------------
__device__ int            g_esize;                       // 8|4|-4|-8
__device__ int8_t         g_spk [T_PAD * K_PAD];         // spikes int8, padded
__device__ int8_t         g_w1s [N_HID * K_PAD];         // w1 int8, padded
__device__ int8_t         g_v1T [(size_t)N_HID * N_HID]; // v1T[k][h] = v1[h][k]
__device__ int8_t         g_w2T [N_HID * N_OUT];         // w2T[k][o] = w2[o][k]
__device__ int            g_in  [T_PAD * N_HID];         // feed-forward currents
__device__ unsigned short g_list[(size_t)T_STEPS * SP_STRIDE]; // spike ids/step
__device__ int            g_cnt [T_STEPS];               // spike count/step
__device__ int            g_ro  [T_STEPS * N_OUT];       // readout currents

// ---------------------------------------------------------------------------
// Dtype-agnostic element load (values all fit int; conversions exact)
// ---------------------------------------------------------------------------
__device__ __forceinline__ int load_elem(const void* p, int es, size_t i) {
    if (es == 8)  return (int)((const long long*)p)[i];
    if (es == 4)  return ((const int*)p)[i];
    if (es == -4) return (int)((const float*)p)[i];
    return (int)((const double*)p)[i];
}

// ---------------------------------------------------------------------------
// Dtype sniffing on w2's raw words (values uniform in [-8,8)).
// ---------------------------------------------------------------------------
__global__ void k_detect(const void* __restrict__ w2) {
    const unsigned* u = (const unsigned*)w2;
    int is_float = 0, odd_ok = 1, even_nz = 0;
    for (int i = 0; i < 512; ++i) {
        unsigned w = u[i];
        unsigned e = (w >> 23) & 0xFFu;
        if (w != 0u && e >= 0x70u && e <= 0x90u) is_float = 1;
        if (i & 1) { if (w != 0u && w != 0xFFFFFFFFu) odd_ok = 0; }
        else       { if (w != 0u) even_nz = 1; }
    }
    g_esize = is_float ? (even_nz ? -4 : -8) : (odd_ok ? 8 : 4);
}

// ---------------------------------------------------------------------------
// Pack kernels
// ---------------------------------------------------------------------------
__global__ void k_pack_spk(const void* __restrict__ spk) {
    int es = g_esize;
    int idx = blockIdx.x * blockDim.x + threadIdx.x;
    if (idx >= T_PAD * K_PAD) return;
    int t = idx / K_PAD, i = idx % K_PAD;
    int8_t v = 0;
    if (t < T_STEPS && i < N_IN) v = (int8_t)load_elem(spk, es, (size_t)t * N_IN + i);
    g_spk[idx] = v;
}

__global__ void k_pack_w1(const void* __restrict__ w1) {
    int es = g_esize;
    int idx = blockIdx.x * blockDim.x + threadIdx.x;
    if (idx >= N_HID * K_PAD) return;
    int h = idx / K_PAD, i = idx % K_PAD;
    int8_t v = 0;
    if (i < N_IN) v = (int8_t)load_elem(w1, es, (size_t)h * N_IN + i);
    g_w1s[idx] = v;
}

// w2[o][k] -> w2T[k][o] int8 (per-spike readout reads 20 contiguous bytes)
__global__ void k_pack_w2(const void* __restrict__ w2) {
    int es = g_esize;
    int idx = blockIdx.x * blockDim.x + threadIdx.x;
    if (idx >= N_OUT * N_HID) return;
    int o = idx / N_HID, k = idx % N_HID;
    g_w2T[k * N_OUT + o] = (int8_t)load_elem(w2, es, (size_t)idx);
}

// Tiled transpose v1[h][k] -> v1T[k][h] (int8)
__global__ void k_v1_transpose(const void* __restrict__ v1) {
    __shared__ int8_t tile[32][33];
    int es = g_esize;
    int bk = blockIdx.x * 32;
    int bh = blockIdx.y * 32;
    int x = threadIdx.x, y = threadIdx.y;
    tile[y][x] = (int8_t)load_elem(v1, es, (size_t)(bh + y) * N_HID + (bk + x));
    __syncthreads();
    g_v1T[(size_t)(bk + y) * N_HID + (bh + x)] = tile[x][y];
}

// ---------------------------------------------------------------------------
// in_all GEMM: g_in[t][h] = sum_i g_spk[t][i] * g_w1s[h][i]
// Each warp computes a 16(T) x 64(H) tile: A fragment reused across 8 N-tiles.
// ---------------------------------------------------------------------------
__global__ __launch_bounds__(256) void k_gemm_in() {
    int warp = (blockIdx.x * blockDim.x + threadIdx.x) >> 5;
    int lane = threadIdx.x & 31;
    int tt = warp / (N_HID / 64);
    int hh = warp % (N_HID / 64);
    int T0 = tt * 16;
    int H0 = hh * 64;

    int grp = lane >> 2;
    int tig = lane & 3;

    int acc[8][4];
    #pragma unroll
    for (int nt = 0; nt < 8; ++nt)
        acc[nt][0] = acc[nt][1] = acc[nt][2] = acc[nt][3] = 0;

    const int8_t* arow0 = g_spk + (size_t)(T0 + grp)     * K_PAD;
    const int8_t* arow1 = g_spk + (size_t)(T0 + grp + 8) * K_PAD;

    for (int k0 = 0; k0 < K_PAD; k0 += 32) {
        int a0 = *(const int*)(arow0 + k0 + tig * 4);
        int a1 = *(const int*)(arow1 + k0 + tig * 4);
        int a2 = *(const int*)(arow0 + k0 + 16 + tig * 4);
        int a3 = *(const int*)(arow1 + k0 + 16 + tig * 4);
        #pragma unroll
        for (int nt = 0; nt < 8; ++nt) {
            const int8_t* brow = g_w1s + (size_t)(H0 + nt * 8 + grp) * K_PAD;
            int b0 = *(const int*)(brow + k0 + tig * 4);
            int b1 = *(const int*)(brow + k0 + 16 + tig * 4);
            asm volatile(
                "mma.sync.aligned.m16n8k32.row.col.s32.s8.s8.s32 "
                "{%0,%1,%2,%3}, {%4,%5,%6,%7}, {%8,%9}, {%0,%1,%2,%3};"
                : "+r"(acc[nt][0]), "+r"(acc[nt][1]), "+r"(acc[nt][2]), "+r"(acc[nt][3])
                : "r"(a0), "r"(a1), "r"(a2), "r"(a3), "r"(b0), "r"(b1));
        }
    }

    #pragma unroll
    for (int nt = 0; nt < 8; ++nt) {
        int* out0 = g_in + (size_t)(T0 + grp)     * N_HID + H0 + nt * 8 + tig * 2;
        int* out1 = g_in + (size_t)(T0 + grp + 8) * N_HID + H0 + nt * 8 + tig * 2;
        out0[0] = acc[nt][0];  out0[1] = acc[nt][1];
        out1[0] = acc[nt][2];  out1[1] = acc[nt][3];
    }
}

// ---------------------------------------------------------------------------
// Persistent single-CTA recurrent kernel — ISSUE-OPTIMIZED.
// 256 threads; thread tid owns neurons h = 16*tid + {0..15}.
// Per spike row: 1 LDG.128 (16 contiguous v1T bytes) + 16 dp4a
//   => ~1.4 issued inst per neuron per spike (vs ~3.5 in R7).
// 2 warps/SMSP => per-step issue ~= 400 inst * 2 = ~800 slots.
// 256 threads => 255-reg cap: ~90 live regs, no spills possible.
//
// Readout deferred to post-kernels (linear filter of recorded spike train).
//
// Sync audit (1 __syncthreads per step): lists double-buffered (RAW and WAR
// across steps separated by the barrier); counters triple-buffered
// read/write/zero rotation (zeroed buffer last read before previous barrier,
// next written after this one); g_cnt STG post-barrier, read only by later
// kernels.
// ---------------------------------------------------------------------------
__global__ __launch_bounds__(256, 1) void k_persist()
{
    __shared__ __align__(16) unsigned short list0[N_HID + 8];
    __shared__ __align__(16) unsigned short list1[N_HID + 8];
    __shared__ int cnt[3];

    const int tid = threadIdx.x;
    if (tid == 0) { cnt[0] = 0; cnt[1] = 0; cnt[2] = 0; }
    __syncthreads();

    int mem[16], syn[16];
    #pragma unroll
    for (int j = 0; j < 16; ++j) { mem[j] = 0; syn[j] = 0; }
    unsigned prev = 0;

    const int hbase = tid * 16;
    const int8_t* v1col = g_v1T + hbase;

    int ir = 2, iw = 0, iz = 1;     // counter rotation: read, write, zero

    for (int t = 0; t < T_STEPS; ++t) {
        unsigned short* wr = (t & 1) ? list1 : list0;   // written this step
        unsigned short* rd = (t & 1) ? list0 : list1;   // written at t-1

        // feed-forward currents for this step's 16 neurons (64 B)
        int iv[16];
        {
            const int4* gp = (const int4*)(g_in + (size_t)t * N_HID + hbase);
            int4 a = gp[0], b = gp[1], c = gp[2], d = gp[3];
            iv[0]=a.x; iv[1]=a.y; iv[2]=a.z; iv[3]=a.w;
            iv[4]=b.x; iv[5]=b.y; iv[6]=b.z; iv[7]=b.w;
            iv[8]=c.x; iv[9]=c.y; iv[10]=c.z; iv[11]=c.w;
            iv[12]=d.x; iv[13]=d.y; iv[14]=d.z; iv[15]=d.w;
        }

        // sparse recurrent feedback from spikes(t-1)
        int n = cnt[ir];
        int fb[16];
        #pragma unroll
        for (int j = 0; j < 16; ++j) fb[j] = 0;

        int i = 0;
        for (; i + 2 <= n; i += 2) {
            unsigned pair = *(const unsigned*)(rd + i);   // 2 indices, 1 LDS
            const int4 wa = *(const int4*)(v1col + (size_t)(pair & 0xFFFFu) * N_HID);
            const int4 wb = *(const int4*)(v1col + (size_t)(pair >> 16)     * N_HID);
            #pragma unroll
            for (int q = 0; q < 4; ++q) {
                int wwa = (q == 0) ? wa.x : (q == 1) ? wa.y : (q == 2) ? wa.z : wa.w;
                int wwb = (q == 0) ? wb.x : (q == 1) ? wb.y : (q == 2) ? wb.z : wb.w;
                fb[q*4+0] = __dp4a(wwa, 0x00000001, fb[q*4+0]);
                fb[q*4+1] = __dp4a(wwa, 0x00000100, fb[q*4+1]);
                fb[q*4+2] = __dp4a(wwa, 0x00010000, fb[q*4+2]);
                fb[q*4+3] = __dp4a(wwa, 0x01000000, fb[q*4+3]);
                fb[q*4+0] = __dp4a(wwb, 0x00000001, fb[q*4+0]);
                fb[q*4+1] = __dp4a(wwb, 0x00000100, fb[q*4+1]);
                fb[q*4+2] = __dp4a(wwb, 0x00010000, fb[q*4+2]);
                fb[q*4+3] = __dp4a(wwb, 0x01000000, fb[q*4+3]);
            }
        }
        if (i < n) {
            int k = rd[i];
            const int4 wa = *(const int4*)(v1col + (size_t)k * N_HID);
            #pragma unroll
            for (int q = 0; q < 4; ++q) {
                int ww = (q == 0) ? wa.x : (q == 1) ? wa.y : (q == 2) ? wa.z : wa.w;
                fb[q*4+0] = __dp4a(ww, 0x00000001, fb[q*4+0]);
                fb[q*4+1] = __dp4a(ww, 0x00000100, fb[q*4+1]);
                fb[q*4+2] = __dp4a(ww, 0x00010000, fb[q*4+2]);
                fb[q*4+3] = __dp4a(ww, 0x01000000, fb[q*4+3]);
            }
        }

        // hidden LIF: reset -> threshold -> decay/integrate; record spikes
        unsigned short* gl = g_list + (size_t)t * SP_STRIDE;
        unsigned newprev = 0;
        #pragma unroll
        for (int j = 0; j < 16; ++j) {
            int m = (prev >> j) & 1 ? 0 : mem[j];
            int o = (m > 1);
            mem[j] = m - (m >> 3) + syn[j];
            syn[j] = syn[j] - (syn[j] >> 4) + iv[j] + fb[j];
            if (o) {
                int pos = atomicAdd(&cnt[iw], 1);
                wr[pos] = (unsigned short)(hbase + j);
                gl[pos] = (unsigned short)(hbase + j);
                newprev |= (1u << j);
            }
        }
        prev = newprev;

        if (tid == 0) cnt[iz] = 0;             // recycle for step t+1

        __syncthreads();                        // single barrier per step

        if (tid == 0) g_cnt[t] = cnt[iw];       // publish count (post-barrier)

        // rotate counter roles
        int t0 = ir; ir = iw; iw = iz; iz = t0;
    }
}

// ---------------------------------------------------------------------------
// Readout currents: ro[t][o] = sum_{k in spikes(t)} w2T[k][o]
// 1000 independent blocks; w2T is L2-resident (80 KB).
// ---------------------------------------------------------------------------
__global__ __launch_bounds__(32) void k_rocur() {
    int t = blockIdx.x;
    int o = threadIdx.x;
    int n = g_cnt[t];
    const unsigned short* gl = g_list + (size_t)t * SP_STRIDE;
    int ro = 0;
    if (o < N_OUT) {
        for (int i = 0; i < n; ++i) {
            int k = gl[i];
            ro += g_w2T[k * N_OUT + o];
        }
        g_ro[t * N_OUT + o] = ro;
    }
}

// ---------------------------------------------------------------------------
// Readout LIF scan: 20 threads, each scans its output over 1000 steps.
// ---------------------------------------------------------------------------
__global__ __launch_bounds__(32) void k_roscan(float* __restrict__ out) {
    int o = threadIdx.x;
    if (o >= N_OUT) return;
    int rmem = 0, rsyn = 0;
    for (int t = 0; t < T_STEPS; t += 4) {
        int r0 = g_ro[(t + 0) * N_OUT + o];
        int r1 = g_ro[(t + 1) * N_OUT + o];
        int r2 = g_ro[(t + 2) * N_OUT + o];
        int r3 = g_ro[(t + 3) * N_OUT + o];
        rmem = rmem - (rmem >> 3) + rsyn;  rsyn = rsyn - (rsyn >> 4) + r0;
        out[(size_t)o * T_STEPS + t + 0] = (float)rmem;
        rmem = rmem - (rmem >> 3) + rsyn;  rsyn = rsyn - (rsyn >> 4) + r1;
        out[(size_t)o * T_STEPS + t + 1] = (float)rmem;
        rmem = rmem - (rmem >> 3) + rsyn;  rsyn = rsyn - (rsyn >> 4) + r2;
        out[(size_t)o * T_STEPS + t + 2] = (float)rmem;
        rmem = rmem - (rmem >> 3) + rsyn;  rsyn = rsyn - (rsyn >> 4) + r3;
        out[(size_t)o * T_STEPS + t + 3] = (float)rmem;
    }
}

// ---------------------------------------------------------------------------
// Launch
// ---------------------------------------------------------------------------
extern "C" void kernel_launch(void* const* d_in, const int* in_sizes, int n_in,
                              void* d_out, int out_size) {
    // Robust input identification: all element counts are distinct.
    const void* spk = d_in[0];
    const void* w1  = d_in[1];
    const void* v1  = d_in[2];
    const void* w2  = d_in[3];
    for (int i = 0; i < n_in && i < 4; ++i) {
        int s = in_sizes[i];
        if      (s == T_STEPS * N_IN)  spk = d_in[i];
        else if (s == N_HID * N_IN)    w1  = d_in[i];
        else if (s == N_HID * N_HID)   v1  = d_in[i];
        else if (s == N_OUT * N_HID)   w2  = d_in[i];
    }

    k_detect<<<1, 1>>>(w2);

    k_pack_spk<<<(T_PAD * K_PAD + 255) / 256, 256>>>(spk);
    k_pack_w1 <<<(N_HID * K_PAD + 255) / 256, 256>>>(w1);
    k_pack_w2 <<<(N_OUT * N_HID + 255) / 256, 256>>>(w2);
    k_v1_transpose<<<dim3(N_HID / 32, N_HID / 32), dim3(32, 32)>>>(v1);

    k_gemm_in<<<(T_PAD / 16) * (N_HID / 64) / 8, 256>>>();

    k_persist<<<1, 256>>>();

    k_rocur<<<T_STEPS, 32>>>();
    k_roscan<<<1, 32>>>((float*)d_out);
}